// round 13
// baseline (speedup 1.0000x reference)
#include <cuda_runtime.h>
#include <cstdint>

#define T_TABLES 4
#define B_BATCH  8192
#define L_LEN    50
#define D_DIM    128
#define VOCAB_N  100000
#define ROWS_TOTAL (T_TABLES * B_BATCH)   // 32768

// Scratch (device globals: allocation-free rule)
__device__ float g_Wc[D_DIM * D_DIM];     // Wc[d][j] = (W3 W2 W1)[j][d]
__device__ float g_bc[D_DIM];

// ---- f32x2 packed helpers -------------------------------------------------
__device__ __forceinline__ void fma2(unsigned long long& d,
                                     unsigned long long a, unsigned long long b) {
    asm("fma.rn.f32x2 %0, %1, %2, %0;" : "+l"(d) : "l"(a), "l"(b));
}
__device__ __forceinline__ unsigned long long add2(unsigned long long a,
                                                   unsigned long long b) {
    unsigned long long r;
    asm("add.rn.f32x2 %0, %1, %2;" : "=l"(r) : "l"(a), "l"(b));
    return r;
}
__device__ __forceinline__ float2 upk(unsigned long long v) {
    float2 r;
    asm("mov.b64 {%0, %1}, %2;" : "=f"(r.x), "=f"(r.y) : "l"(v));
    return r;
}

// ---------------------------------------------------------------------------
// prep: ONE kernel. blocks 0..127: column d of M = W3·W2·W1 via two chained
// mat-vecs; coalesced stores. block 128: bc = (b1 W2^T + b2) W3^T + b3.
// ---------------------------------------------------------------------------
__global__ void prep_kernel(const float* __restrict__ W1, const float* __restrict__ b1,
                            const float* __restrict__ W2, const float* __restrict__ b2,
                            const float* __restrict__ W3, const float* __restrict__ b3) {
    __shared__ float v[D_DIM];
    __shared__ float y[D_DIM];
    const int tid = threadIdx.x;

    if (blockIdx.x < D_DIM) {
        const int d = blockIdx.x;
        v[tid] = W1[tid * D_DIM + d];                       // W1 column d
        __syncthreads();
        const float4* W2r = (const float4*)(W2 + tid * D_DIM);
        float s = 0.f;
#pragma unroll
        for (int k = 0; k < 32; ++k) {                      // MLP=32
            const float4 w = __ldg(&W2r[k]);
            s += w.x * v[k * 4] + w.y * v[k * 4 + 1];
            s += w.z * v[k * 4 + 2] + w.w * v[k * 4 + 3];
        }
        y[tid] = s;
        __syncthreads();
        const float4* W3r = (const float4*)(W3 + tid * D_DIM);
        float s2 = 0.f;
#pragma unroll
        for (int k = 0; k < 32; ++k) {
            const float4 w = __ldg(&W3r[k]);
            s2 += w.x * y[k * 4] + w.y * y[k * 4 + 1];
            s2 += w.z * y[k * 4 + 2] + w.w * y[k * 4 + 3];
        }
        g_Wc[d * D_DIM + tid] = s2;
    } else {
        v[tid] = b1[tid];
        __syncthreads();
        const float4* W2r = (const float4*)(W2 + tid * D_DIM);
        float s = b2[tid];
#pragma unroll
        for (int k = 0; k < 32; ++k) {
            const float4 w = __ldg(&W2r[k]);
            s += w.x * v[k * 4] + w.y * v[k * 4 + 1];
            s += w.z * v[k * 4 + 2] + w.w * v[k * 4 + 3];
        }
        y[tid] = s;
        __syncthreads();
        const float4* W3r = (const float4*)(W3 + tid * D_DIM);
        float s2 = b3[tid];
#pragma unroll
        for (int k = 0; k < 32; ++k) {
            const float4 w = __ldg(&W3r[k]);
            s2 += w.x * y[k * 4] + w.y * y[k * 4 + 1];
            s2 += w.z * y[k * 4 + 2] + w.w * y[k * 4 + 3];
        }
        g_bc[tid] = s2;
    }
}

// ---------------------------------------------------------------------------
// Fused (R11 cache policies, REGISTER-DIET Phase A):
//   - Phase A unroll-2 (2 in-flight loads, 2 accumulator pairs) — per-warp
//     MLP proven non-binding (4->8 neutral); frees ~16 regs so ptxas can
//     naturally reach <=51 regs -> 5 CTAs/SM (warp count IS binding)
//   - table loads __ldcg; Wc/bc __ldg; out __stcs; NO reg cap, NO barriers
// grid = 1024 x 256; 32 KB static smem.
// ---------------------------------------------------------------------------
__global__ __launch_bounds__(256)
void fused_kernel(const int* __restrict__ indices,
                  const int* __restrict__ lengths,
                  const float* __restrict__ tables,
                  float* __restrict__ out) {
    __shared__ float sp[8 * 4 * 2 * D_DIM];        // 32 KB: per-warp duplicated pooled

    const int tid  = threadIdx.x;
    const int warp = tid >> 5, lane = tid & 31;
    const int row0 = (blockIdx.x * 8 + warp) * 4;
    float* my = sp + warp * 4 * 2 * D_DIM;         // 4 rows x 256 floats (dup pairs)

    // ---- Phase A: gather + pool 4 rows (lane owns one float4 of D) ----
#pragma unroll 1
    for (int r = 0; r < 4; ++r) {
        const int g   = row0 + r;
        const int t   = g >> 13;                    // B = 8192
        const int len = lengths[g];
        const int* idxp = indices + (size_t)g * L_LEN;

        const int i_lo = idxp[lane];
        const int i_hi = (lane < (L_LEN - 32)) ? idxp[32 + lane] : 0;

        const float4* tab =
            (const float4*)tables + (size_t)t * ((size_t)VOCAB_N * (D_DIM / 4));

        ulonglong2 A0 = {0ull, 0ull}, A1 = A0;

        auto getidx = [&](int p) -> int {
            return (p < 32) ? __shfl_sync(0xffffffffu, i_lo, p)
                            : __shfl_sync(0xffffffffu, i_hi, p - 32);
        };

        int l = 0;
        for (; l + 1 < len; l += 2) {              // MLP = 2, minimal live regs
            const int j0 = getidx(l + 0);
            const int j1 = getidx(l + 1);
            const ulonglong2 v0 = __ldcg((const ulonglong2*)(tab + (size_t)j0 * 32 + lane));
            const ulonglong2 v1 = __ldcg((const ulonglong2*)(tab + (size_t)j1 * 32 + lane));
            A0.x = add2(A0.x, v0.x); A0.y = add2(A0.y, v0.y);
            A1.x = add2(A1.x, v1.x); A1.y = add2(A1.y, v1.y);
        }
        if (l < len) {
            const int j0 = getidx(l);
            const ulonglong2 v0 = __ldcg((const ulonglong2*)(tab + (size_t)j0 * 32 + lane));
            A0.x = add2(A0.x, v0.x); A0.y = add2(A0.y, v0.y);
        }

        const unsigned long long rlo = add2(A0.x, A1.x);
        const unsigned long long rhi = add2(A0.y, A1.y);
        const float2 f0 = upk(rlo);     // (p[c], p[c+1])   c = lane*4
        const float2 f1 = upk(rhi);     // (p[c+2], p[c+3])

        // duplicated-pair layout: pos 2d, 2d+1 both hold p[d]
        float4 s0, s1;
        s0.x = f0.x; s0.y = f0.x; s0.z = f0.y; s0.w = f0.y;
        s1.x = f1.x; s1.y = f1.x; s1.z = f1.y; s1.w = f1.y;
        *(float4*)&my[r * 2 * D_DIM + lane * 8]     = s0;
        *(float4*)&my[r * 2 * D_DIM + lane * 8 + 4] = s1;
    }
    __syncwarp();

    // ---- Phase B: out[r][:] = pooled[r][:] @ Wc + bc  (packed f32x2) ----
    const ulonglong2 bc2 = __ldg((const ulonglong2*)g_bc + lane);
    unsigned long long olo[4], ohi[4];
#pragma unroll
    for (int r = 0; r < 4; ++r) { olo[r] = bc2.x; ohi[r] = bc2.y; }

    const ulonglong2* WcU = (const ulonglong2*)g_Wc;   // row d: 32 x ulonglong2

#pragma unroll 2
    for (int d2 = 0; d2 < 64; ++d2) {              // 2 Wc rows per iter (8 w regs)
        const ulonglong2 w0 = __ldg(&WcU[(size_t)(d2 * 2 + 0) * 32 + lane]);
        const ulonglong2 w1 = __ldg(&WcU[(size_t)(d2 * 2 + 1) * 32 + lane]);
        const int poff = d2 * 4;                    // dup-pair offset of these 2 k's
#pragma unroll
        for (int r = 0; r < 4; ++r) {
            const ulonglong2 q0 = *(const ulonglong2*)&my[r * 2 * D_DIM + poff];
            fma2(olo[r], q0.x, w0.x); fma2(ohi[r], q0.x, w0.y);
            fma2(olo[r], q0.y, w1.x); fma2(ohi[r], q0.y, w1.y);
        }
    }

#pragma unroll
    for (int r = 0; r < 4; ++r) {
        ulonglong2 res; res.x = olo[r]; res.y = ohi[r];
        __stcs((ulonglong2*)(out + (size_t)(row0 + r) * D_DIM + lane * 4), res);
    }
}

// ---------------------------------------------------------------------------
extern "C" void kernel_launch(void* const* d_in, const int* in_sizes, int n_in,
                              void* d_out, int out_size) {
    const int*   indices = (const int*)d_in[0];
    const int*   lengths = (const int*)d_in[1];
    const float* tables  = (const float*)d_in[2];
    const float* W1      = (const float*)d_in[3];
    const float* b1      = (const float*)d_in[4];
    const float* W2      = (const float*)d_in[5];
    const float* b2      = (const float*)d_in[6];
    const float* W3      = (const float*)d_in[7];
    const float* b3      = (const float*)d_in[8];
    float* out = (float*)d_out;

    prep_kernel<<<D_DIM + 1, D_DIM>>>(W1, b1, W2, b2, W3, b3);
    fused_kernel<<<ROWS_TOTAL / 32, 256>>>(indices, lengths, tables, out);
}

// round 14
// speedup vs baseline: 1.1908x; 1.1908x over previous
#include <cuda_runtime.h>
#include <cuda_fp16.h>
#include <cstdint>

#define T_TABLES 4
#define B_BATCH  8192
#define L_LEN    50
#define D_DIM    128
#define VOCAB_N  100000
#define ROWS_TOTAL (T_TABLES * B_BATCH)   // 32768

// Scratch (device globals: allocation-free rule)
__device__ __half g_Wch[D_DIM * D_DIM];   // fp16 Wc: Wch[d][j] = (W3 W2 W1)[j][d]
__device__ float  g_bc[D_DIM];

// ---- f32x2 packed helpers -------------------------------------------------
__device__ __forceinline__ void fma2(unsigned long long& d,
                                     unsigned long long a, unsigned long long b) {
    asm("fma.rn.f32x2 %0, %1, %2, %0;" : "+l"(d) : "l"(a), "l"(b));
}
__device__ __forceinline__ unsigned long long add2(unsigned long long a,
                                                   unsigned long long b) {
    unsigned long long r;
    asm("add.rn.f32x2 %0, %1, %2;" : "=l"(r) : "l"(a), "l"(b));
    return r;
}
__device__ __forceinline__ float2 upk(unsigned long long v) {
    float2 r;
    asm("mov.b64 {%0, %1}, %2;" : "=f"(r.x), "=f"(r.y) : "l"(v));
    return r;
}
// half2 (packed in u32) -> f32x2 operand (u64)
__device__ __forceinline__ unsigned long long h2w(uint32_t h2pack) {
    __half2 h = *(__half2*)&h2pack;
    float2 f = __half22float2(h);
    unsigned long long r;
    asm("mov.b64 %0, {%1, %2};" : "=l"(r) : "f"(f.x), "f"(f.y));
    return r;
}

// ---------------------------------------------------------------------------
// prep: ONE kernel. blocks 0..127: column d of M = W3·W2·W1 via two chained
// mat-vecs; stores Wc row d as fp16 (coalesced). block 128: bc (f32).
// ---------------------------------------------------------------------------
__global__ void prep_kernel(const float* __restrict__ W1, const float* __restrict__ b1,
                            const float* __restrict__ W2, const float* __restrict__ b2,
                            const float* __restrict__ W3, const float* __restrict__ b3) {
    __shared__ float v[D_DIM];
    __shared__ float y[D_DIM];
    const int tid = threadIdx.x;

    if (blockIdx.x < D_DIM) {
        const int d = blockIdx.x;
        v[tid] = W1[tid * D_DIM + d];                       // W1 column d
        __syncthreads();
        const float4* W2r = (const float4*)(W2 + tid * D_DIM);
        float s = 0.f;
#pragma unroll
        for (int k = 0; k < 32; ++k) {                      // MLP=32
            const float4 w = __ldg(&W2r[k]);
            s += w.x * v[k * 4] + w.y * v[k * 4 + 1];
            s += w.z * v[k * 4 + 2] + w.w * v[k * 4 + 3];
        }
        y[tid] = s;
        __syncthreads();
        const float4* W3r = (const float4*)(W3 + tid * D_DIM);
        float s2 = 0.f;
#pragma unroll
        for (int k = 0; k < 32; ++k) {
            const float4 w = __ldg(&W3r[k]);
            s2 += w.x * y[k * 4] + w.y * y[k * 4 + 1];
            s2 += w.z * y[k * 4 + 2] + w.w * y[k * 4 + 3];
        }
        g_Wch[d * D_DIM + tid] = __float2half(s2);
    } else {
        v[tid] = b1[tid];
        __syncthreads();
        const float4* W2r = (const float4*)(W2 + tid * D_DIM);
        float s = b2[tid];
#pragma unroll
        for (int k = 0; k < 32; ++k) {
            const float4 w = __ldg(&W2r[k]);
            s += w.x * v[k * 4] + w.y * v[k * 4 + 1];
            s += w.z * v[k * 4 + 2] + w.w * v[k * 4 + 3];
        }
        y[tid] = s;
        __syncthreads();
        const float4* W3r = (const float4*)(W3 + tid * D_DIM);
        float s2 = b3[tid];
#pragma unroll
        for (int k = 0; k < 32; ++k) {
            const float4 w = __ldg(&W3r[k]);
            s2 += w.x * y[k * 4] + w.y * y[k * 4 + 1];
            s2 += w.z * y[k * 4 + 2] + w.w * y[k * 4 + 3];
        }
        g_bc[tid] = s2;
    }
}

// ---------------------------------------------------------------------------
// Fused = R11 best config + fp16 Wc in Phase B:
//   - Phase A: unroll-4 (MLP knee), shfl indices, __ldcg table loads
//   - Phase B: Wc as fp16 LDG.64 (2 wf vs 4 per load), convert->f32, f32 acc
//   - Wc/bc .ca; out __stcs; NO reg cap, NO block barriers
// grid = 1024 x 256; 32 KB static smem; natural regs.
// ---------------------------------------------------------------------------
__global__ __launch_bounds__(256)
void fused_kernel(const int* __restrict__ indices,
                  const int* __restrict__ lengths,
                  const float* __restrict__ tables,
                  float* __restrict__ out) {
    __shared__ float sp[8 * 4 * 2 * D_DIM];        // 32 KB: per-warp duplicated pooled

    const int tid  = threadIdx.x;
    const int warp = tid >> 5, lane = tid & 31;
    const int row0 = (blockIdx.x * 8 + warp) * 4;
    float* my = sp + warp * 4 * 2 * D_DIM;         // 4 rows x 256 floats (dup pairs)

    // ---- Phase A: gather + pool 4 rows (lane owns one float4 of D) ----
#pragma unroll 1
    for (int r = 0; r < 4; ++r) {
        const int g   = row0 + r;
        const int t   = g >> 13;                    // B = 8192
        const int len = lengths[g];
        const int* idxp = indices + (size_t)g * L_LEN;

        const int i_lo = idxp[lane];
        const int i_hi = (lane < (L_LEN - 32)) ? idxp[32 + lane] : 0;

        const float4* tab =
            (const float4*)tables + (size_t)t * ((size_t)VOCAB_N * (D_DIM / 4));

        ulonglong2 A0 = {0ull, 0ull}, A1 = A0, A2 = A0, A3 = A0;

        auto getidx = [&](int p) -> int {
            return (p < 32) ? __shfl_sync(0xffffffffu, i_lo, p)
                            : __shfl_sync(0xffffffffu, i_hi, p - 32);
        };

        int l = 0;
        for (; l + 3 < len; l += 4) {
            const int j0 = getidx(l + 0);
            const int j1 = getidx(l + 1);
            const int j2 = getidx(l + 2);
            const int j3 = getidx(l + 3);
            const ulonglong2 v0 = __ldcg((const ulonglong2*)(tab + (size_t)j0 * 32 + lane));
            const ulonglong2 v1 = __ldcg((const ulonglong2*)(tab + (size_t)j1 * 32 + lane));
            const ulonglong2 v2 = __ldcg((const ulonglong2*)(tab + (size_t)j2 * 32 + lane));
            const ulonglong2 v3 = __ldcg((const ulonglong2*)(tab + (size_t)j3 * 32 + lane));
            A0.x = add2(A0.x, v0.x); A0.y = add2(A0.y, v0.y);
            A1.x = add2(A1.x, v1.x); A1.y = add2(A1.y, v1.y);
            A2.x = add2(A2.x, v2.x); A2.y = add2(A2.y, v2.y);
            A3.x = add2(A3.x, v3.x); A3.y = add2(A3.y, v3.y);
        }
        for (; l < len; ++l) {
            const int j0 = getidx(l);
            const ulonglong2 v0 = __ldcg((const ulonglong2*)(tab + (size_t)j0 * 32 + lane));
            A0.x = add2(A0.x, v0.x); A0.y = add2(A0.y, v0.y);
        }

        const unsigned long long rlo = add2(add2(A0.x, A1.x), add2(A2.x, A3.x));
        const unsigned long long rhi = add2(add2(A0.y, A1.y), add2(A2.y, A3.y));
        const float2 f0 = upk(rlo);     // (p[c], p[c+1])   c = lane*4
        const float2 f1 = upk(rhi);     // (p[c+2], p[c+3])

        // duplicated-pair layout: pos 2d, 2d+1 both hold p[d]
        float4 s0, s1;
        s0.x = f0.x; s0.y = f0.x; s0.z = f0.y; s0.w = f0.y;
        s1.x = f1.x; s1.y = f1.x; s1.z = f1.y; s1.w = f1.y;
        *(float4*)&my[r * 2 * D_DIM + lane * 8]     = s0;
        *(float4*)&my[r * 2 * D_DIM + lane * 8 + 4] = s1;
    }
    __syncwarp();

    // ---- Phase B: out[r][:] = pooled[r][:] @ Wc + bc  (fp16 W, f32 acc) ----
    const ulonglong2 bc2 = __ldg((const ulonglong2*)g_bc + lane);
    unsigned long long olo[4], ohi[4];
#pragma unroll
    for (int r = 0; r < 4; ++r) { olo[r] = bc2.x; ohi[r] = bc2.y; }

    // row d of Wch: 128 halves = 32 uint2; lane owns cols lane*4..lane*4+3
    const uint2* WcH = (const uint2*)g_Wch;

#pragma unroll 4
    for (int d4 = 0; d4 < 32; ++d4) {
        const uint2 h0 = __ldg(&WcH[(size_t)(d4 * 4 + 0) * 32 + lane]);
        const uint2 h1 = __ldg(&WcH[(size_t)(d4 * 4 + 1) * 32 + lane]);
        const uint2 h2 = __ldg(&WcH[(size_t)(d4 * 4 + 2) * 32 + lane]);
        const uint2 h3 = __ldg(&WcH[(size_t)(d4 * 4 + 3) * 32 + lane]);
        const unsigned long long w0x = h2w(h0.x), w0y = h2w(h0.y);
        const unsigned long long w1x = h2w(h1.x), w1y = h2w(h1.y);
        const unsigned long long w2x = h2w(h2.x), w2y = h2w(h2.y);
        const unsigned long long w3x = h2w(h3.x), w3y = h2w(h3.y);
#pragma unroll
        for (int r = 0; r < 4; ++r) {
            const ulonglong2 q0 = *(const ulonglong2*)&my[r * 2 * D_DIM + d4 * 8];
            const ulonglong2 q1 = *(const ulonglong2*)&my[r * 2 * D_DIM + d4 * 8 + 4];
            fma2(olo[r], q0.x, w0x); fma2(ohi[r], q0.x, w0y);
            fma2(olo[r], q0.y, w1x); fma2(ohi[r], q0.y, w1y);
            fma2(olo[r], q1.x, w2x); fma2(ohi[r], q1.x, w2y);
            fma2(olo[r], q1.y, w3x); fma2(ohi[r], q1.y, w3y);
        }
    }

#pragma unroll
    for (int r = 0; r < 4; ++r) {
        ulonglong2 res; res.x = olo[r]; res.y = ohi[r];
        __stcs((ulonglong2*)(out + (size_t)(row0 + r) * D_DIM + lane * 4), res);
    }
}

// ---------------------------------------------------------------------------
extern "C" void kernel_launch(void* const* d_in, const int* in_sizes, int n_in,
                              void* d_out, int out_size) {
    const int*   indices = (const int*)d_in[0];
    const int*   lengths = (const int*)d_in[1];
    const float* tables  = (const float*)d_in[2];
    const float* W1      = (const float*)d_in[3];
    const float* b1      = (const float*)d_in[4];
    const float* W2      = (const float*)d_in[5];
    const float* b2      = (const float*)d_in[6];
    const float* W3      = (const float*)d_in[7];
    const float* b3      = (const float*)d_in[8];
    float* out = (float*)d_out;

    prep_kernel<<<D_DIM + 1, D_DIM>>>(W1, b1, W2, b2, W3, b3);
    fused_kernel<<<ROWS_TOTAL / 32, 256>>>(indices, lengths, tables, out);
}